// round 4
// baseline (speedup 1.0000x reference)
#include <cuda_runtime.h>
#include <cstdint>

#define BB 4
#define NN 50000
#define EE 800000
#define FF 128
#define NBLK 49   // ceil(NN/1024)

// ---------------- scratch (__device__ globals: allocation-free) ----------------
__device__ float g_h[(size_t)BB * NN * FF];   // projected features h = x @ W^T
__device__ int   g_cnt[NN];                   // per-row edge counts
__device__ int   g_off[NN + 1];               // CSR row offsets
__device__ int   g_pos[NN];                   // scatter cursors
__device__ int   g_erow[EE];                  // edge rows as int32
__device__ int   g_ecol[EE];                  // edge cols as int32
__device__ int   g_scol[EE];                  // edge cols sorted by row
__device__ float g_sval[EE];                  // edge vals sorted by row
__device__ int   g_bsum[NBLK];                // scan block sums
__device__ int   g_idx64;                     // 1 if edge indices are int64

// ---------------- dtype detection --------------------------------------------
// int64 values in [0, 50000) have every odd 32-bit word == 0 (little-endian).
// Random int32 row indices make that pattern astronomically unlikely.
__global__ void detect_kernel(const unsigned int* __restrict__ p) {
    if (threadIdx.x == 0 && blockIdx.x == 0) {
        int all0 = 1;
        for (int i = 1; i < 128; i += 2)
            if (p[i] != 0u) all0 = 0;
        g_idx64 = all0;
    }
}

// ---------------- index convert + histogram (fused) ---------------------------
__global__ void zero_kernel() {
    int i = blockIdx.x * blockDim.x + threadIdx.x;
    if (i < NN) g_cnt[i] = 0;
}

__global__ void convert_kernel(const void* __restrict__ erow,
                               const void* __restrict__ ecol) {
    int e = blockIdx.x * blockDim.x + threadIdx.x;
    if (e >= EE) return;
    int r, c;
    if (g_idx64) {
        r = (int)((const long long*)erow)[e];
        c = (int)((const long long*)ecol)[e];
    } else {
        r = ((const int*)erow)[e];
        c = ((const int*)ecol)[e];
    }
    g_erow[e] = r;
    g_ecol[e] = c;
    atomicAdd(&g_cnt[r], 1);
}

// ---------------- GEMM: h[b,n,:] = x[b,n,:] @ W^T  (W is [F_OUT, F_IN]) -------
__global__ void gemm_kernel(const float* __restrict__ x, const float* __restrict__ W) {
    extern __shared__ float sm[];
    float* Wt = sm;             // [128][128]: Wt[k*128 + o] = W[o*128 + k]
    float* xs = sm + FF * FF;   // [32][128]

    for (int i = threadIdx.x; i < FF * FF; i += blockDim.x) {
        int o = i >> 7, k = i & 127;
        Wt[k * FF + o] = W[i];
    }
    __syncthreads();

    const int warp = threadIdx.x >> 5;
    const int lane = threadIdx.x & 31;
    const float4* Wt4 = (const float4*)Wt;
    const int ngroups = (BB * NN) / 32;  // 6250, exact

    for (int g = blockIdx.x; g < ngroups; g += gridDim.x) {
        const size_t base = (size_t)g * 32;
        __syncthreads();  // previous iteration's xs readers done
        {   // stage 32 rows = 1024 float4 with 256 threads
            const float4* xg = (const float4*)(x + base * FF);
            float4* xs4 = (float4*)xs;
            #pragma unroll
            for (int i = 0; i < 4; i++)
                xs4[threadIdx.x + i * 256] = xg[threadIdx.x + i * 256];
        }
        __syncthreads();

        const int r0 = warp * 4;
        float4 a0 = {0,0,0,0}, a1 = {0,0,0,0}, a2 = {0,0,0,0}, a3 = {0,0,0,0};
        const float* x0 = xs + (r0 + 0) * FF;
        const float* x1 = xs + (r0 + 1) * FF;
        const float* x2 = xs + (r0 + 2) * FF;
        const float* x3 = xs + (r0 + 3) * FF;

        #pragma unroll 8
        for (int k = 0; k < FF; k++) {
            float4 w = Wt4[k * 32 + lane];
            float v;
            v = x0[k]; a0.x += v * w.x; a0.y += v * w.y; a0.z += v * w.z; a0.w += v * w.w;
            v = x1[k]; a1.x += v * w.x; a1.y += v * w.y; a1.z += v * w.z; a1.w += v * w.w;
            v = x2[k]; a2.x += v * w.x; a2.y += v * w.y; a2.z += v * w.z; a2.w += v * w.w;
            v = x3[k]; a3.x += v * w.x; a3.y += v * w.y; a3.z += v * w.z; a3.w += v * w.w;
        }

        float4* hp = (float4*)(g_h + (base + r0) * FF);
        hp[lane]          = a0;
        hp[32 + lane]     = a1;
        hp[64 + lane]     = a2;
        hp[96 + lane]     = a3;
    }
}

// ---------------- CSR build ---------------------------------------------------
// inclusive scan per 1024-chunk -> g_off (temp), block totals -> g_bsum
__global__ void scanA_kernel() {
    __shared__ int smv[1024];
    int i = blockIdx.x * 1024 + threadIdx.x;
    int v = (i < NN) ? g_cnt[i] : 0;
    smv[threadIdx.x] = v;
    __syncthreads();
    for (int d = 1; d < 1024; d <<= 1) {
        int t = (threadIdx.x >= d) ? smv[threadIdx.x - d] : 0;
        __syncthreads();
        smv[threadIdx.x] += t;
        __syncthreads();
    }
    if (i < NN) g_off[i] = smv[threadIdx.x];
    if (threadIdx.x == 1023) g_bsum[blockIdx.x] = smv[1023];
}

// serial exclusive scan of the 49 block sums (tiny)
__global__ void scanB_kernel() {
    if (threadIdx.x == 0 && blockIdx.x == 0) {
        int run = 0;
        for (int b = 0; b < NBLK; b++) {
            int t = g_bsum[b];
            g_bsum[b] = run;
            run += t;
        }
    }
}

// convert to global exclusive offsets, init cursors, close CSR
__global__ void scanC_kernel() {
    int i = blockIdx.x * blockDim.x + threadIdx.x;
    if (i < NN) {
        int excl = g_off[i] - g_cnt[i] + g_bsum[i >> 10];
        g_off[i] = excl;
        g_pos[i] = excl;
    }
    if (i == 0) g_off[NN] = EE;
}

__global__ void scatter_kernel(const float* __restrict__ evals) {
    int e = blockIdx.x * blockDim.x + threadIdx.x;
    if (e < EE) {
        int r = g_erow[e];
        int p = atomicAdd(&g_pos[r], 1);
        g_scol[p] = g_ecol[e];
        g_sval[p] = evals[e];
    }
}

// ---------------- SpMM: one warp per (batch,row) ------------------------------
// Batch-major warp indexing so consecutive CTAs share one batch's h (25.6 MB,
// L2-resident) while gathering.
__global__ void spmm_kernel(float* __restrict__ out) {
    int wg = (blockIdx.x * blockDim.x + threadIdx.x) >> 5;
    int lane = threadIdx.x & 31;
    if (wg >= BB * NN) return;
    int b = wg / NN;
    int r = wg - b * NN;

    int s = g_off[r];
    int e = g_off[r + 1];
    const float* hb = g_h + (size_t)b * NN * FF;

    float4 acc = {0, 0, 0, 0};
    for (int i = s; i < e; i++) {
        int   c = g_scol[i];
        float v = g_sval[i];
        float4 hv = ((const float4*)(hb + (size_t)c * FF))[lane];
        acc.x += v * hv.x;
        acc.y += v * hv.y;
        acc.z += v * hv.z;
        acc.w += v * hv.w;
    }
    ((float4*)(out + ((size_t)b * NN + r) * FF))[lane] = acc;
}

// ---------------- launch ------------------------------------------------------
extern "C" void kernel_launch(void* const* d_in, const int* in_sizes, int n_in,
                              void* d_out, int out_size) {
    const float* x     = (const float*)d_in[0];
    const float* W     = (const float*)d_in[1];
    const void*  erow  = d_in[2];
    const void*  ecol  = d_in[3];
    const float* evals = (const float*)d_in[4];
    float*       out   = (float*)d_out;

    const int SMEM_GEMM = (FF * FF + 32 * FF) * (int)sizeof(float);  // 80 KB
    cudaFuncSetAttribute(gemm_kernel, cudaFuncAttributeMaxDynamicSharedMemorySize, SMEM_GEMM);

    gemm_kernel<<<296, 256, SMEM_GEMM>>>(x, W);

    detect_kernel<<<1, 32>>>((const unsigned int*)erow);
    zero_kernel<<<(NN + 255) / 256, 256>>>();
    convert_kernel<<<(EE + 255) / 256, 256>>>(erow, ecol);
    scanA_kernel<<<NBLK, 1024>>>();
    scanB_kernel<<<1, 32>>>();
    scanC_kernel<<<(NN + 255) / 256, 256>>>();
    scatter_kernel<<<(EE + 255) / 256, 256>>>(evals);

    spmm_kernel<<<(BB * NN * 32) / 256, 256>>>(out);
}

// round 6
// speedup vs baseline: 1.4272x; 1.4272x over previous
#include <cuda_runtime.h>
#include <cstdint>

#define BB 4
#define NN 50000
#define EE 800000
#define FF 128
#define NBLK 49           // ceil(NN/1024)
#define MROWS (BB * NN)   // 200000, = 12500 * 16 exactly
#define NTILES 12500      // 16-row warp tiles

// ---------------- scratch (__device__ globals: allocation-free) ----------------
__device__ float    g_h[(size_t)BB * NN * FF];   // projected features h = x @ W^T
__device__ int      g_cnt[NN];                   // per-row edge counts
__device__ int      g_off[NN + 1];               // CSR row offsets
__device__ int      g_pos[NN];                   // scatter cursors
__device__ int      g_erow[EE];                  // edge rows as int32
__device__ int      g_ecol[EE];                  // edge cols as int32
__device__ int      g_scol[EE];                  // edge cols sorted by row
__device__ float    g_sval[EE];                  // edge vals sorted by row
__device__ int      g_bsum[NBLK];                // scan block sums
__device__ int      g_idx64;                     // 1 if edge indices are int64
__device__ uint32_t g_Bhi[8 * 16 * 32 * 2];      // W bf16-hi fragments, pre-swizzled
__device__ uint32_t g_Blo[8 * 16 * 32 * 2];      // W bf16-lo fragments

// ---------------- bf16 split helpers ------------------------------------------
__device__ __forceinline__ uint32_t pack_bf16_hi(float e0, float e1) {
    // lower 16 bits = e0 (even index), upper = e1
    uint32_t r;
    asm("cvt.rn.bf16x2.f32 %0, %1, %2;" : "=r"(r) : "f"(e1), "f"(e0));
    return r;
}
__device__ __forceinline__ uint32_t pack_bf16_lo(uint32_t hi, float e0, float e1) {
    float h0 = __uint_as_float(hi << 16);
    float h1 = __uint_as_float(hi & 0xffff0000u);
    return pack_bf16_hi(e0 - h0, e1 - h1);
}

#define MMA16816(C, A0, A1, A2, A3, B0, B1)                                        \
    asm volatile("mma.sync.aligned.m16n8k16.row.col.f32.bf16.bf16.f32 "            \
                 "{%0,%1,%2,%3}, {%4,%5,%6,%7}, {%8,%9}, {%0,%1,%2,%3};"           \
                 : "+f"((C)[0]), "+f"((C)[1]), "+f"((C)[2]), "+f"((C)[3])          \
                 : "r"(A0), "r"(A1), "r"(A2), "r"(A3), "r"(B0), "r"(B1))

// ---------------- W -> pre-swizzled B fragments --------------------------------
// B (col-major k x n for mma): B[k][n] = W[n*128 + k].
// Fragment for (k_step, n_tile): lane l: grp=l>>2 -> n = n_tile*8+grp, tig=l&3;
// reg rr: k0 = k_step*16 + tig*2 + rr*8, pack {W[n][k0], W[n][k0+1]} lo-first.
__global__ void prepB_kernel(const float* __restrict__ W) {
    int t = blockIdx.x * blockDim.x + threadIdx.x;   // 4096 threads
    if (t >= 4096) return;
    int ks = t >> 9, nt = (t >> 5) & 15, lane = t & 31;
    int grp = lane >> 2, tig = lane & 3;
    int n = nt * 8 + grp;
    #pragma unroll
    for (int rr = 0; rr < 2; rr++) {
        int k0 = ks * 16 + tig * 2 + rr * 8;
        float e0 = W[n * FF + k0];
        float e1 = W[n * FF + k0 + 1];
        uint32_t hi = pack_bf16_hi(e0, e1);
        uint32_t lo = pack_bf16_lo(hi, e0, e1);
        int idx = ((ks * 16 + nt) * 32 + lane) * 2 + rr;
        g_Bhi[idx] = hi;
        g_Blo[idx] = lo;
    }
}

// ---------------- GEMM: h = x @ W^T via split-bf16 tensor MMA ------------------
// One warp per 16-row tile. k-outer / n-inner: A frags (8 regs) rebuilt per
// k_step from gmem float2 loads; 64 fp32 accums held across the k loop.
__global__ void __launch_bounds__(256) gemm_mma_kernel(const float* __restrict__ x) {
    extern __shared__ uint32_t sB[];
    uint32_t* sBhi = sB;           // [8][16][32][2]
    uint32_t* sBlo = sB + 8192;

    for (int i = threadIdx.x; i < 8192; i += 256) {
        sBhi[i] = g_Bhi[i];
        sBlo[i] = g_Blo[i];
    }
    __syncthreads();

    const int lane = threadIdx.x & 31;
    const int warp = threadIdx.x >> 5;
    const int grp = lane >> 2, tig = lane & 3;
    const int nwarps = gridDim.x * 8;

    for (int tile = blockIdx.x * 8 + warp; tile < NTILES; tile += nwarps) {
        const int row0 = tile * 16;
        const float* xr0 = x + (size_t)(row0 + grp) * FF;       // rows grp, grp+8
        const float* xr1 = x + (size_t)(row0 + grp + 8) * FF;

        float acc[16][4];
        #pragma unroll
        for (int nt = 0; nt < 16; nt++)
            #pragma unroll
            for (int j = 0; j < 4; j++) acc[nt][j] = 0.0f;

        #pragma unroll 2
        for (int ks = 0; ks < 8; ks++) {
            const int c0 = ks * 16 + tig * 2;
            float2 f0 = *(const float2*)(xr0 + c0);
            float2 f1 = *(const float2*)(xr1 + c0);
            float2 f2 = *(const float2*)(xr0 + c0 + 8);
            float2 f3 = *(const float2*)(xr1 + c0 + 8);

            uint32_t ah0 = pack_bf16_hi(f0.x, f0.y), al0 = pack_bf16_lo(ah0, f0.x, f0.y);
            uint32_t ah1 = pack_bf16_hi(f1.x, f1.y), al1 = pack_bf16_lo(ah1, f1.x, f1.y);
            uint32_t ah2 = pack_bf16_hi(f2.x, f2.y), al2 = pack_bf16_lo(ah2, f2.x, f2.y);
            uint32_t ah3 = pack_bf16_hi(f3.x, f3.y), al3 = pack_bf16_lo(ah3, f3.x, f3.y);

            const uint32_t* bh = sBhi + (ks * 16 * 32 + lane) * 2;
            const uint32_t* bl = sBlo + (ks * 16 * 32 + lane) * 2;
            #pragma unroll
            for (int nt = 0; nt < 16; nt++) {
                uint32_t b0h = bh[nt * 64], b1h = bh[nt * 64 + 1];
                uint32_t b0l = bl[nt * 64], b1l = bl[nt * 64 + 1];
                MMA16816(acc[nt], ah0, ah1, ah2, ah3, b0h, b1h);  // hi*hi
                MMA16816(acc[nt], ah0, ah1, ah2, ah3, b0l, b1l);  // hi*lo
                MMA16816(acc[nt], al0, al1, al2, al3, b0h, b1h);  // lo*hi
            }
        }

        // store: c0,c1 -> (row grp, col nt*8+tig*2); c2,c3 -> row grp+8
        float* h0 = g_h + (size_t)(row0 + grp) * FF;
        float* h1 = g_h + (size_t)(row0 + grp + 8) * FF;
        #pragma unroll
        for (int nt = 0; nt < 16; nt++) {
            int col = nt * 8 + tig * 2;
            *(float2*)(h0 + col) = make_float2(acc[nt][0], acc[nt][1]);
            *(float2*)(h1 + col) = make_float2(acc[nt][2], acc[nt][3]);
        }
    }
}

// ---------------- CSR build ----------------------------------------------------
// zero counters + detect edge-index dtype (int64 values < 2^32 have every odd
// 32-bit word zero; random int32 indices make that pattern impossible).
__global__ void zero_kernel(const unsigned int* __restrict__ erow_words) {
    int i = blockIdx.x * blockDim.x + threadIdx.x;
    if (i < NN) g_cnt[i] = 0;
    if (i == 0) {
        int all0 = 1;
        for (int w = 1; w < 128; w += 2)
            if (erow_words[w] != 0u) all0 = 0;
        g_idx64 = all0;
    }
}

__global__ void convert_kernel(const void* __restrict__ erow,
                               const void* __restrict__ ecol) {
    int e = blockIdx.x * blockDim.x + threadIdx.x;
    if (e >= EE) return;
    int r, c;
    if (g_idx64) {
        r = (int)((const long long*)erow)[e];
        c = (int)((const long long*)ecol)[e];
    } else {
        r = ((const int*)erow)[e];
        c = ((const int*)ecol)[e];
    }
    g_erow[e] = r;
    g_ecol[e] = c;
    atomicAdd(&g_cnt[r], 1);
}

// inclusive scan per 1024-chunk -> g_off (temp), block totals -> g_bsum
__global__ void scanA_kernel() {
    __shared__ int smv[1024];
    int i = blockIdx.x * 1024 + threadIdx.x;
    int v = (i < NN) ? g_cnt[i] : 0;
    smv[threadIdx.x] = v;
    __syncthreads();
    for (int d = 1; d < 1024; d <<= 1) {
        int t = (threadIdx.x >= d) ? smv[threadIdx.x - d] : 0;
        __syncthreads();
        smv[threadIdx.x] += t;
        __syncthreads();
    }
    if (i < NN) g_off[i] = smv[threadIdx.x];
    if (threadIdx.x == 1023) g_bsum[blockIdx.x] = smv[1023];
}

__global__ void scanB_kernel() {
    if (threadIdx.x == 0 && blockIdx.x == 0) {
        int run = 0;
        for (int b = 0; b < NBLK; b++) {
            int t = g_bsum[b];
            g_bsum[b] = run;
            run += t;
        }
    }
}

__global__ void scanC_kernel() {
    int i = blockIdx.x * blockDim.x + threadIdx.x;
    if (i < NN) {
        int excl = g_off[i] - g_cnt[i] + g_bsum[i >> 10];
        g_off[i] = excl;
        g_pos[i] = excl;
    }
    if (i == 0) g_off[NN] = EE;
}

__global__ void scatter_kernel(const float* __restrict__ evals) {
    int e = blockIdx.x * blockDim.x + threadIdx.x;
    if (e < EE) {
        int r = g_erow[e];
        int p = atomicAdd(&g_pos[r], 1);
        g_scol[p] = g_ecol[e];
        g_sval[p] = evals[e];
    }
}

// ---------------- SpMM: one warp per (batch,row) --------------------------------
__global__ void spmm_kernel(float* __restrict__ out) {
    int wg = (blockIdx.x * blockDim.x + threadIdx.x) >> 5;
    int lane = threadIdx.x & 31;
    if (wg >= BB * NN) return;
    int b = wg / NN;
    int r = wg - b * NN;

    int s = g_off[r];
    int e = g_off[r + 1];
    const float* hb = g_h + (size_t)b * NN * FF;

    float4 acc = {0, 0, 0, 0};
    int i = s;
    for (; i + 1 < e; i += 2) {
        int   c0 = g_scol[i],     c1 = g_scol[i + 1];
        float v0 = g_sval[i],     v1 = g_sval[i + 1];
        float4 h0 = ((const float4*)(hb + (size_t)c0 * FF))[lane];
        float4 h1 = ((const float4*)(hb + (size_t)c1 * FF))[lane];
        acc.x += v0 * h0.x + v1 * h1.x;
        acc.y += v0 * h0.y + v1 * h1.y;
        acc.z += v0 * h0.z + v1 * h1.z;
        acc.w += v0 * h0.w + v1 * h1.w;
    }
    if (i < e) {
        int   c = g_scol[i];
        float v = g_sval[i];
        float4 hv = ((const float4*)(hb + (size_t)c * FF))[lane];
        acc.x += v * hv.x;
        acc.y += v * hv.y;
        acc.z += v * hv.z;
        acc.w += v * hv.w;
    }
    ((float4*)(out + ((size_t)b * NN + r) * FF))[lane] = acc;
}

// ---------------- launch --------------------------------------------------------
extern "C" void kernel_launch(void* const* d_in, const int* in_sizes, int n_in,
                              void* d_out, int out_size) {
    const float* x     = (const float*)d_in[0];
    const float* W     = (const float*)d_in[1];
    const void*  erow  = d_in[2];
    const void*  ecol  = d_in[3];
    const float* evals = (const float*)d_in[4];
    float*       out   = (float*)d_out;

    const int SMEM_B = 2 * 8192 * (int)sizeof(uint32_t);  // 64 KB
    cudaFuncSetAttribute(gemm_mma_kernel, cudaFuncAttributeMaxDynamicSharedMemorySize, SMEM_B);

    prepB_kernel<<<16, 256>>>(W);
    gemm_mma_kernel<<<296, 256, SMEM_B>>>(x);

    zero_kernel<<<(NN + 255) / 256, 256>>>((const unsigned int*)erow);
    convert_kernel<<<(EE + 255) / 256, 256>>>(erow, ecol);
    scanA_kernel<<<NBLK, 1024>>>();
    scanB_kernel<<<1, 32>>>();
    scanC_kernel<<<(NN + 255) / 256, 256>>>();
    scatter_kernel<<<(EE + 255) / 256, 256>>>(evals);

    spmm_kernel<<<(BB * NN * 32) / 256, 256>>>(out);
}